// round 1
// baseline (speedup 1.0000x reference)
#include <cuda_runtime.h>

// ---------------------------------------------------------------------------
// SpGraphAttentionLayer (GAT forward), fused.
// N=50000, D=128, O=128, R=64, E=1e6.
//
// Math:
//   xs = x @ a_src^T, xd = x @ a_dst^T            (per-node, precomputed)
//   m[e]     = xs[src] + xd[dst] + emb[e] @ a_rel^T
//   score[e] = sdot_s[src] + sdot_d[dst] + emb[e]·c     (c = a2 @ a_rel)
//   ee[e]    = exp(-leaky(score))
//   h[n]     = sum_{e: src=e} ee*m ;  rs[n] = sum ee
//   out      = elu(h / rs)
// ---------------------------------------------------------------------------

#define NMAX 50000

__device__ float g_xsd[(size_t)NMAX * 256];   // [n][0:128]=xs, [n][128:256]=xd
__device__ float g_sdot[(size_t)NMAX * 2];    // [2n]=xs[n]·a2, [2n+1]=xd[n]·a2
__device__ float g_u[320];                    // [0:128]=u_s, [128:256]=u_d, [256:320]=c
__device__ float g_rowsum[NMAX];

__device__ __forceinline__ void fma2(unsigned long long &acc,
                                     unsigned long long a, unsigned long long b) {
    asm("fma.rn.f32x2 %0, %1, %2, %0;" : "+l"(acc) : "l"(a), "l"(b));
}
__device__ __forceinline__ float2 unpack2(unsigned long long v) {
    float2 r;
    asm("mov.b64 {%0, %1}, %2;" : "=f"(r.x), "=f"(r.y) : "l"(v));
    return r;
}

// ---------------------------------------------------------------------------
// Zero the accumulators (d_out is poisoned before timing; graph replays).
// ---------------------------------------------------------------------------
__global__ void zero_kernel(float* __restrict__ h, int nh, int nr) {
    int stride = gridDim.x * blockDim.x;
    int i = blockIdx.x * blockDim.x + threadIdx.x;
    for (int j = i; j < nh; j += stride) h[j] = 0.f;
    for (int j = i; j < nr; j += stride) g_rowsum[j] = 0.f;
}

// ---------------------------------------------------------------------------
// u_s[k] = sum_o a2[o]*a[o][k]; u_d[k] = ...a[o][128+k]; c[k] = ...a[o][256+k]
// One block, 320 threads (one per output column of the 320-wide a matrix).
// ---------------------------------------------------------------------------
__global__ void vec_kernel(const float* __restrict__ a, const float* __restrict__ a2) {
    __shared__ float a2s[128];
    int t = threadIdx.x;
    if (t < 128) a2s[t] = a2[t];
    __syncthreads();
    if (t < 320) {
        float acc = 0.f;
        #pragma unroll 8
        for (int o = 0; o < 128; o++) acc += a2s[o] * a[o * 320 + t];
        g_u[t] = acc;
    }
}

// ---------------------------------------------------------------------------
// xsd[n][o] : o<128 -> x[n]·a[o][0:128] ; o>=128 -> x[n]·a[o-128][128:256]
// Block = 256 threads, 16 nodes per block, thread t owns output column t.
// ---------------------------------------------------------------------------
__global__ void __launch_bounds__(256) prep_kernel(const float* __restrict__ x,
                                                   const float* __restrict__ a, int N) {
    __shared__ float xs_sm[16 * 128];
    int t = threadIdx.x;
    int n0 = blockIdx.x * 16;

    // stage 16 node rows (16*128 f32 = 512 float4)
    const float4* xg = (const float4*)(x + (size_t)n0 * 128);
    size_t lim4 = (size_t)N * 32;  // total float4 in x
    float4 z4 = make_float4(0.f, 0.f, 0.f, 0.f);
    ((float4*)xs_sm)[t]       = ((size_t)n0 * 32 + t       < lim4) ? xg[t]       : z4;
    ((float4*)xs_sm)[t + 256] = ((size_t)n0 * 32 + t + 256 < lim4) ? xg[t + 256] : z4;
    __syncthreads();

    const float* arow = (t < 128) ? (a + (size_t)t * 320)
                                  : (a + (size_t)(t - 128) * 320 + 128);
    unsigned long long acc[16];
    #pragma unroll
    for (int n = 0; n < 16; n++) acc[n] = 0ull;

    #pragma unroll 4
    for (int k4 = 0; k4 < 32; k4++) {
        ulonglong2 wv = ((const ulonglong2*)arow)[k4];
        #pragma unroll
        for (int n = 0; n < 16; n++) {
            ulonglong2 xv = ((const ulonglong2*)(xs_sm + n * 128))[k4];
            fma2(acc[n], xv.x, wv.x);
            fma2(acc[n], xv.y, wv.y);
        }
    }
    #pragma unroll
    for (int n = 0; n < 16; n++) {
        if (n0 + n < N) {
            float2 f = unpack2(acc[n]);
            g_xsd[(size_t)(n0 + n) * 256 + t] = f.x + f.y;
        }
    }
}

// ---------------------------------------------------------------------------
// sdot_s[n] = x[n]·u_s ; sdot_d[n] = x[n]·u_d.  One warp per node.
// ---------------------------------------------------------------------------
__global__ void __launch_bounds__(128) sdot_kernel(const float* __restrict__ x, int N) {
    __shared__ float us[256];
    int t = threadIdx.x;
    us[t] = g_u[t];
    us[t + 128] = g_u[t + 128];
    __syncthreads();

    int n = blockIdx.x * 4 + (t >> 5);
    if (n >= N) return;
    int lane = t & 31;
    float ps = 0.f, pd = 0.f;
    #pragma unroll
    for (int j = 0; j < 4; j++) {
        float xv = x[(size_t)n * 128 + lane + 32 * j];
        ps += xv * us[lane + 32 * j];
        pd += xv * us[128 + lane + 32 * j];
    }
    #pragma unroll
    for (int off = 16; off; off >>= 1) {
        ps += __shfl_xor_sync(0xffffffffu, ps, off);
        pd += __shfl_xor_sync(0xffffffffu, pd, off);
    }
    if (lane == 0) { g_sdot[2 * n] = ps; g_sdot[2 * n + 1] = pd; }
}

// ---------------------------------------------------------------------------
// Edge kernel: block = 128 threads = 2 edge-teams of 64 threads.
// Thread owns outputs o0=2*t64, o0+1. a_rel rows register-resident (f32x2
// packed over k). emb broadcast via LDG.128. Scatter via red.global.add.v2.
// ---------------------------------------------------------------------------
__global__ void __launch_bounds__(128) edge_kernel(
    const int* __restrict__ edge1, const float* __restrict__ emb1,
    const int* __restrict__ edge2, const float* __restrict__ emb2,
    const float* __restrict__ a, float* __restrict__ h,
    int E1, int E2)
{
    __shared__ float c_sm[64];
    int t = threadIdx.x;
    int half = t >> 6;
    int t64 = t & 63;
    int lane = t & 31;
    int o0 = t64 * 2;

    if (t < 64) c_sm[t] = g_u[256 + t];

    // a_rel rows o0, o0+1 into registers, packed as f32x2 pairs over k
    unsigned long long wA[32], wB[32];
    {
        const ulonglong2* rA = (const ulonglong2*)(a + (size_t)o0 * 320 + 256);
        const ulonglong2* rB = (const ulonglong2*)(a + (size_t)(o0 + 1) * 320 + 256);
        #pragma unroll
        for (int i = 0; i < 16; i++) { ulonglong2 v = rA[i]; wA[2*i] = v.x; wA[2*i+1] = v.y; }
        #pragma unroll
        for (int i = 0; i < 16; i++) { ulonglong2 v = rB[i]; wB[2*i] = v.x; wB[2*i+1] = v.y; }
    }
    __syncthreads();

    long long E = (long long)E1 + E2;
    for (long long eb = (long long)blockIdx.x * 2; eb < E; eb += (long long)gridDim.x * 2) {
        long long e = eb + half;
        if (e >= E) continue;  // uniform per warp

        int src, dst;
        const float* emb;
        if (e < E1) {
            src = edge1[e]; dst = edge1[E1 + e];
            emb = emb1 + e * 64;
        } else {
            long long e2 = e - E1;
            src = edge2[e2]; dst = edge2[E2 + e2];
            emb = emb2 + e2 * 64;
        }

        // --- score (each warp computes the full 64-dot independently) ---
        float p = emb[lane] * c_sm[lane] + emb[lane + 32] * c_sm[lane + 32];
        #pragma unroll
        for (int off = 16; off; off >>= 1) p += __shfl_xor_sync(0xffffffffu, p, off);
        float score = p + g_sdot[2 * src] + g_sdot[2 * dst + 1];
        float pw = score > 0.f ? score : 0.2f * score;
        float ee = __expf(-pw);
        if (t64 == 0) atomicAdd(&g_rowsum[src], ee);

        // --- GEMV: m_rel[o0], m_rel[o0+1] = emb · a_rel[o0/o0+1] ---
        unsigned long long a0 = 0ull, a1 = 0ull, b0 = 0ull, b1 = 0ull;
        const ulonglong2* ev = (const ulonglong2*)emb;
        #pragma unroll
        for (int i = 0; i < 16; i++) {
            ulonglong2 v = ev[i];          // broadcast across warp
            fma2(a0, v.x, wA[2*i]);
            fma2(a1, v.y, wA[2*i+1]);
            fma2(b0, v.x, wB[2*i]);
            fma2(b1, v.y, wB[2*i+1]);
        }
        float2 fa0 = unpack2(a0), fa1 = unpack2(a1);
        float2 fb0 = unpack2(b0), fb1 = unpack2(b1);
        float mr0 = (fa0.x + fa0.y) + (fa1.x + fa1.y);
        float mr1 = (fb0.x + fb0.y) + (fb1.x + fb1.y);

        float2 xs = *(const float2*)&g_xsd[(size_t)src * 256 + o0];
        float2 xd = *(const float2*)&g_xsd[(size_t)dst * 256 + 128 + o0];
        float v0 = ee * (xs.x + xd.x + mr0);
        float v1 = ee * (xs.y + xd.y + mr1);

        float* dp = h + (size_t)src * 128 + o0;
        asm volatile("red.global.add.v2.f32 [%0], {%1, %2};"
                     :: "l"(dp), "f"(v0), "f"(v1) : "memory");
    }
}

// ---------------------------------------------------------------------------
// out = elu(h / rowsum), in place on d_out. elu(x) = x>0 ? x : expm1(x).
// ---------------------------------------------------------------------------
__global__ void final_kernel(float* __restrict__ h, int N) {
    int total = N * 128;
    int stride = gridDim.x * blockDim.x;
    for (int i = blockIdx.x * blockDim.x + threadIdx.x; i < total; i += stride) {
        float rs = g_rowsum[i >> 7];
        rs = (rs == 0.f) ? 1e-12f : rs;
        float v = h[i] / rs;
        h[i] = v > 0.f ? v : expm1f(v);
    }
}

// ---------------------------------------------------------------------------
extern "C" void kernel_launch(void* const* d_in, const int* in_sizes, int n_in,
                              void* d_out, int out_size) {
    const float* x     = (const float*)d_in[0];
    const int*   edge1 = (const int*)  d_in[1];
    const float* emb1  = (const float*)d_in[2];
    const int*   edge2 = (const int*)  d_in[3];
    const float* emb2  = (const float*)d_in[4];
    const float* a     = (const float*)d_in[5];
    const float* a2    = (const float*)d_in[6];
    float* h = (float*)d_out;

    int N  = in_sizes[0] / 128;
    int E1 = in_sizes[1] / 2;
    int E2 = in_sizes[3] / 2;

    zero_kernel<<<1024, 256>>>(h, N * 128, N);
    vec_kernel<<<1, 320>>>(a, a2);
    prep_kernel<<<(N + 15) / 16, 256>>>(x, a, N);
    sdot_kernel<<<(N + 3) / 4, 128>>>(x, N);
    edge_kernel<<<1776, 128>>>(edge1, emb1, edge2, emb2, a, h, E1, E2);
    final_kernel<<<1024, 256>>>(h, N);
}

// round 2
// speedup vs baseline: 2.3517x; 2.3517x over previous
#include <cuda_runtime.h>

// ---------------------------------------------------------------------------
// SpGraphAttentionLayer (GAT forward), GEMM-tiled edge kernel.
// N=50000, D=128, O=128, R=64, E=1e6.
//
//   xs = x @ a_src^T, xd = x @ a_dst^T            (per-node, precomputed)
//   m[e]     = xs[src] + xd[dst] + emb[e] @ a_rel^T
//   score[e] = sdot_s[src] + sdot_d[dst] + emb[e]·c     (c = a2 @ a_rel)
//   ee[e]    = exp(-leaky(score))
//   acc[n]   = sum_{e: src=n} ee*(xd[dst] + m_rel)  ;  rs[n] = sum ee
//   out[n]   = elu( xs[n] + acc[n]/rs[n] )   (xs term folded out of edge loop)
// ---------------------------------------------------------------------------

#define NMAX 50000
#define GAT_ALPHA 0.2f

__device__ float g_xsd[(size_t)NMAX * 256];   // [n][0:128]=xs, [n][128:256]=xd
__device__ float g_sdot[(size_t)NMAX * 2];    // [2n]=xs[n]·a2, [2n+1]=xd[n]·a2
__device__ float g_u[320];                    // [0:128]=u_s, [128:256]=u_d, [256:320]=c
__device__ float g_rowsum[NMAX];

__device__ __forceinline__ void fma2(unsigned long long &acc,
                                     unsigned long long a, unsigned long long b) {
    asm("fma.rn.f32x2 %0, %1, %2, %0;" : "+l"(acc) : "l"(a), "l"(b));
}
__device__ __forceinline__ float2 unpack2(unsigned long long v) {
    float2 r;
    asm("mov.b64 {%0, %1}, %2;" : "=f"(r.x), "=f"(r.y) : "l"(v));
    return r;
}
__device__ __forceinline__ unsigned long long pack_dup(float w) {
    unsigned long long r;
    asm("mov.b64 %0, {%1, %1};" : "=l"(r) : "f"(w));
    return r;
}

// ---------------------------------------------------------------------------
__global__ void zero_kernel(float* __restrict__ h, int nh, int nr) {
    int stride = gridDim.x * blockDim.x;
    int i = blockIdx.x * blockDim.x + threadIdx.x;
    for (int j = i; j < nh; j += stride) h[j] = 0.f;
    for (int j = i; j < nr; j += stride) g_rowsum[j] = 0.f;
}

// ---------------------------------------------------------------------------
__global__ void vec_kernel(const float* __restrict__ a, const float* __restrict__ a2) {
    __shared__ float a2s[128];
    int t = threadIdx.x;
    if (t < 128) a2s[t] = a2[t];
    __syncthreads();
    if (t < 320) {
        float acc = 0.f;
        #pragma unroll 8
        for (int o = 0; o < 128; o++) acc += a2s[o] * a[o * 320 + t];
        g_u[t] = acc;
    }
}

// ---------------------------------------------------------------------------
__global__ void __launch_bounds__(256) prep_kernel(const float* __restrict__ x,
                                                   const float* __restrict__ a, int N) {
    __shared__ float xs_sm[16 * 128];
    int t = threadIdx.x;
    int n0 = blockIdx.x * 16;

    const float4* xg = (const float4*)(x + (size_t)n0 * 128);
    size_t lim4 = (size_t)N * 32;
    float4 z4 = make_float4(0.f, 0.f, 0.f, 0.f);
    ((float4*)xs_sm)[t]       = ((size_t)n0 * 32 + t       < lim4) ? xg[t]       : z4;
    ((float4*)xs_sm)[t + 256] = ((size_t)n0 * 32 + t + 256 < lim4) ? xg[t + 256] : z4;
    __syncthreads();

    const float* arow = (t < 128) ? (a + (size_t)t * 320)
                                  : (a + (size_t)(t - 128) * 320 + 128);
    unsigned long long acc[16];
    #pragma unroll
    for (int n = 0; n < 16; n++) acc[n] = 0ull;

    #pragma unroll 4
    for (int k4 = 0; k4 < 32; k4++) {
        ulonglong2 wv = ((const ulonglong2*)arow)[k4];
        #pragma unroll
        for (int n = 0; n < 16; n++) {
            ulonglong2 xv = ((const ulonglong2*)(xs_sm + n * 128))[k4];
            fma2(acc[n], xv.x, wv.x);
            fma2(acc[n], xv.y, wv.y);
        }
    }
    #pragma unroll
    for (int n = 0; n < 16; n++) {
        if (n0 + n < N) {
            float2 f = unpack2(acc[n]);
            g_xsd[(size_t)(n0 + n) * 256 + t] = f.x + f.y;
        }
    }
}

// ---------------------------------------------------------------------------
__global__ void __launch_bounds__(128) sdot_kernel(const float* __restrict__ x, int N) {
    __shared__ float us[256];
    int t = threadIdx.x;
    us[t] = g_u[t];
    us[t + 128] = g_u[t + 128];
    __syncthreads();

    int n = blockIdx.x * 4 + (t >> 5);
    if (n >= N) return;
    int lane = t & 31;
    float ps = 0.f, pd = 0.f;
    #pragma unroll
    for (int j = 0; j < 4; j++) {
        float xv = x[(size_t)n * 128 + lane + 32 * j];
        ps += xv * us[lane + 32 * j];
        pd += xv * us[128 + lane + 32 * j];
    }
    #pragma unroll
    for (int off = 16; off; off >>= 1) {
        ps += __shfl_xor_sync(0xffffffffu, ps, off);
        pd += __shfl_xor_sync(0xffffffffu, pd, off);
    }
    if (lane == 0) { g_sdot[2 * n] = ps; g_sdot[2 * n + 1] = pd; }
}

// ---------------------------------------------------------------------------
// Edge kernel: 256 threads, tile = 64 edges x 128 outputs, K=64 in 2 halves.
// warp w owns edges e0=w*8..e0+7 ; lane owns outputs o0=lane*4..o0+3.
// acc packed f32x2 over edge pairs.
// ---------------------------------------------------------------------------
__device__ __forceinline__ void prefetch_emb(
    long long t, int half, const float* __restrict__ emb1,
    const float* __restrict__ emb2, long long E1, long long E,
    int tid, float4& r0, float4& r1)
{
    int e_loc = tid >> 2, q = tid & 3;
    long long ge = t * 64 + e_loc;
    if (ge >= E) ge = E - 1;
    const float* ep = (ge < E1) ? (emb1 + ge * 64) : (emb2 + (ge - E1) * 64);
    ep += half * 32 + q * 8;
    r0 = __ldg((const float4*)ep);
    r1 = __ldg((const float4*)(ep + 4));
}

__device__ __forceinline__ void sts_emb(float* emb_sm, int tid, float4 r0, float4 r1) {
    int e_loc = tid >> 2, q = tid & 3;
    int kb = q * 8;
    emb_sm[(kb + 0) * 64 + e_loc] = r0.x;
    emb_sm[(kb + 1) * 64 + e_loc] = r0.y;
    emb_sm[(kb + 2) * 64 + e_loc] = r0.z;
    emb_sm[(kb + 3) * 64 + e_loc] = r0.w;
    emb_sm[(kb + 4) * 64 + e_loc] = r1.x;
    emb_sm[(kb + 5) * 64 + e_loc] = r1.y;
    emb_sm[(kb + 6) * 64 + e_loc] = r1.z;
    emb_sm[(kb + 7) * 64 + e_loc] = r1.w;
}

__global__ void __launch_bounds__(256) edge_kernel(
    const int* __restrict__ edge1, const float* __restrict__ emb1,
    const int* __restrict__ edge2, const float* __restrict__ emb2,
    const float* __restrict__ a, float* __restrict__ hout,
    int E1i, int E2i)
{
    __shared__ float emb_sm[32 * 64];     // [k_local][e]  (8 KB, one K-half)
    __shared__ float w_sm[64 * 128];      // [k][o]        (32 KB)
    __shared__ float c_sm[64];
    __shared__ int   srcs[64], dsts[64];
    __shared__ float ss_sm[64], sd_sm[64], ee_sm[64];

    const long long E1 = E1i, E2 = E2i;
    const long long E = E1 + E2;
    const long long T = (E + 63) >> 6;

    int tid = threadIdx.x;
    int warp = tid >> 5, lane = tid & 31;
    int e0 = warp * 8;
    int o0 = lane * 4;

    // w_sm[k][o] = a_rel[o][k]
    for (int i = tid; i < 8192; i += 256) {
        int o = i & 127, k = i >> 7;
        w_sm[k * 128 + o] = a[(size_t)o * 320 + 256 + k];
    }
    if (tid < 64) c_sm[tid] = g_u[256 + tid];

    long long t = blockIdx.x;
    long long stride = gridDim.x;

    float4 rA0, rA1, rB0, rB1;
    int ps = 0, pd = 0;
    float pss = 0.f, psd = 0.f;

    if (t < T) {
        prefetch_emb(t, 0, emb1, emb2, E1, E, tid, rA0, rA1);
        if (tid < 64) {
            long long ge = t * 64 + tid;
            if (ge < E) {
                if (ge < E1) { ps = edge1[ge]; pd = edge1[E1 + ge]; }
                else { long long g2 = ge - E1; ps = edge2[g2]; pd = edge2[E2 + g2]; }
                pss = g_sdot[2 * ps];
                psd = g_sdot[2 * pd + 1];
            }
        }
    }
    __syncthreads();   // w_sm / c_sm ready

    for (; t < T; t += stride) {
        // stage tile t
        if (tid < 64) { srcs[tid] = ps; dsts[tid] = pd; ss_sm[tid] = pss; sd_sm[tid] = psd; }
        sts_emb(emb_sm, tid, rA0, rA1);
        __syncthreads();

        prefetch_emb(t, 1, emb1, emb2, E1, E, tid, rB0, rB1);

        unsigned long long acc[4][4];
        #pragma unroll
        for (int p = 0; p < 4; p++)
            #pragma unroll
            for (int j = 0; j < 4; j++) acc[p][j] = 0ull;
        float part = 0.f;

        int eS = e0 + (lane & 7);
        int kg = lane >> 3;

        // ---- GEMM half 0 (k = 0..31) ----
        #pragma unroll 8
        for (int k2 = 0; k2 < 32; k2++) {
            ulonglong2 P01 = *(const ulonglong2*)&emb_sm[k2 * 64 + e0];
            ulonglong2 P23 = *(const ulonglong2*)&emb_sm[k2 * 64 + e0 + 4];
            float4 wv = *(const float4*)&w_sm[k2 * 128 + o0];
            unsigned long long w0 = pack_dup(wv.x), w1 = pack_dup(wv.y);
            unsigned long long w2 = pack_dup(wv.z), w3 = pack_dup(wv.w);
            fma2(acc[0][0], P01.x, w0); fma2(acc[0][1], P01.x, w1);
            fma2(acc[0][2], P01.x, w2); fma2(acc[0][3], P01.x, w3);
            fma2(acc[1][0], P01.y, w0); fma2(acc[1][1], P01.y, w1);
            fma2(acc[1][2], P01.y, w2); fma2(acc[1][3], P01.y, w3);
            fma2(acc[2][0], P23.x, w0); fma2(acc[2][1], P23.x, w1);
            fma2(acc[2][2], P23.x, w2); fma2(acc[2][3], P23.x, w3);
            fma2(acc[3][0], P23.y, w0); fma2(acc[3][1], P23.y, w1);
            fma2(acc[3][2], P23.y, w2); fma2(acc[3][3], P23.y, w3);
        }
        // score partial, half 0
        #pragma unroll
        for (int i = 0; i < 8; i++) {
            int kl = kg * 8 + i;
            part += emb_sm[kl * 64 + eS] * c_sm[kl];
        }
        __syncthreads();   // half 0 consumed

        sts_emb(emb_sm, tid, rB0, rB1);
        __syncthreads();

        if (t + stride < T) {
            prefetch_emb(t + stride, 0, emb1, emb2, E1, E, tid, rA0, rA1);
            if (tid < 64) {
                long long ge = (t + stride) * 64 + tid;
                ps = 0; pd = 0; pss = 0.f; psd = 0.f;
                if (ge < E) {
                    if (ge < E1) { ps = edge1[ge]; pd = edge1[E1 + ge]; }
                    else { long long g2 = ge - E1; ps = edge2[g2]; pd = edge2[E2 + g2]; }
                    pss = g_sdot[2 * ps];
                    psd = g_sdot[2 * pd + 1];
                }
            }
        }

        // ---- GEMM half 1 (k = 32..63) ----
        #pragma unroll 8
        for (int k2 = 0; k2 < 32; k2++) {
            int k = 32 + k2;
            ulonglong2 P01 = *(const ulonglong2*)&emb_sm[k2 * 64 + e0];
            ulonglong2 P23 = *(const ulonglong2*)&emb_sm[k2 * 64 + e0 + 4];
            float4 wv = *(const float4*)&w_sm[k * 128 + o0];
            unsigned long long w0 = pack_dup(wv.x), w1 = pack_dup(wv.y);
            unsigned long long w2 = pack_dup(wv.z), w3 = pack_dup(wv.w);
            fma2(acc[0][0], P01.x, w0); fma2(acc[0][1], P01.x, w1);
            fma2(acc[0][2], P01.x, w2); fma2(acc[0][3], P01.x, w3);
            fma2(acc[1][0], P01.y, w0); fma2(acc[1][1], P01.y, w1);
            fma2(acc[1][2], P01.y, w2); fma2(acc[1][3], P01.y, w3);
            fma2(acc[2][0], P23.x, w0); fma2(acc[2][1], P23.x, w1);
            fma2(acc[2][2], P23.x, w2); fma2(acc[2][3], P23.x, w3);
            fma2(acc[3][0], P23.y, w0); fma2(acc[3][1], P23.y, w1);
            fma2(acc[3][2], P23.y, w2); fma2(acc[3][3], P23.y, w3);
        }
        // score partial, half 1
        #pragma unroll
        for (int i = 0; i < 8; i++) {
            int kl = kg * 8 + i;
            part += emb_sm[kl * 64 + eS] * c_sm[32 + kl];
        }

        // reduce score partials across the 4 k-groups
        part += __shfl_xor_sync(0xffffffffu, part, 8);
        part += __shfl_xor_sync(0xffffffffu, part, 16);

        int el = e0 + (lane & 7);
        float sc = part + ss_sm[el] + sd_sm[el];
        float pw = sc > 0.f ? sc : GAT_ALPHA * sc;
        float eev = __expf(-pw);
        if (lane < 8) {
            ee_sm[el] = eev;
            long long ge = t * 64 + el;
            if (ge < E) atomicAdd(&g_rowsum[srcs[el]], eev);
        }
        __syncwarp();

        // ---- epilogue: v = ee * (xd[dst] + m_rel), scatter-add to hout[src] ----
        #pragma unroll
        for (int p = 0; p < 4; p++) {
            float2 m0 = unpack2(acc[p][0]);
            float2 m1 = unpack2(acc[p][1]);
            float2 m2 = unpack2(acc[p][2]);
            float2 m3 = unpack2(acc[p][3]);
            int eb = e0 + 2 * p;
            #pragma unroll
            for (int hh = 0; hh < 2; hh++) {
                int ei = eb + hh;
                long long ge = t * 64 + ei;
                if (ge < E) {
                    int s = srcs[ei], d = dsts[ei];
                    float eev2 = ee_sm[ei];
                    float4 xd = *(const float4*)&g_xsd[(size_t)d * 256 + 128 + o0];
                    float v0 = eev2 * (xd.x + (hh ? m0.y : m0.x));
                    float v1 = eev2 * (xd.y + (hh ? m1.y : m1.x));
                    float v2 = eev2 * (xd.z + (hh ? m2.y : m2.x));
                    float v3 = eev2 * (xd.w + (hh ? m3.y : m3.x));
                    float* dp = hout + (size_t)s * 128 + o0;
                    asm volatile("red.global.add.v2.f32 [%0], {%1, %2};"
                                 :: "l"(dp), "f"(v0), "f"(v1) : "memory");
                    asm volatile("red.global.add.v2.f32 [%0], {%1, %2};"
                                 :: "l"(dp + 2), "f"(v2), "f"(v3) : "memory");
                }
            }
        }
        __syncthreads();   // all smem consumed before next tile overwrite
    }
}

// ---------------------------------------------------------------------------
// out = elu( xs + acc/rowsum ); rowsum==0 -> 0 (no incident edges).
// ---------------------------------------------------------------------------
__global__ void final_kernel(float* __restrict__ hout, int N) {
    int total = N * 128;
    int stride = gridDim.x * blockDim.x;
    for (int i = blockIdx.x * blockDim.x + threadIdx.x; i < total; i += stride) {
        int n = i >> 7;
        float rs = g_rowsum[n];
        float v;
        if (rs > 0.f) {
            v = g_xsd[(size_t)n * 256 + (i & 127)] + hout[i] / rs;
        } else {
            v = 0.f;
        }
        hout[i] = v > 0.f ? v : expm1f(v);
    }
}

// ---------------------------------------------------------------------------
extern "C" void kernel_launch(void* const* d_in, const int* in_sizes, int n_in,
                              void* d_out, int out_size) {
    const float* x     = (const float*)d_in[0];
    const int*   edge1 = (const int*)  d_in[1];
    const float* emb1  = (const float*)d_in[2];
    const int*   edge2 = (const int*)  d_in[3];
    const float* emb2  = (const float*)d_in[4];
    const float* a     = (const float*)d_in[5];
    const float* a2    = (const float*)d_in[6];
    float* hout = (float*)d_out;

    int N  = in_sizes[0] / 128;
    int E1 = in_sizes[1] / 2;
    int E2 = in_sizes[3] / 2;

    zero_kernel<<<1024, 256>>>(hout, N * 128, N);
    vec_kernel<<<1, 320>>>(a, a2);
    prep_kernel<<<(N + 15) / 16, 256>>>(x, a, N);
    sdot_kernel<<<(N + 3) / 4, 128>>>(x, N);
    edge_kernel<<<592, 256>>>(edge1, emb1, edge2, emb2, a, hout, E1, E2);
    final_kernel<<<1024, 256>>>(hout, N);
}

// round 3
// speedup vs baseline: 2.3599x; 1.0035x over previous
#include <cuda_runtime.h>

// ---------------------------------------------------------------------------
// SpGraphAttentionLayer (GAT forward).  N=50000, D=128, O=128, R=64, E=1e6.
//
//   xs = x @ a_src^T, xd = x @ a_dst^T            (per-node, precomputed)
//   m[e]     = xs[src] + xd[dst] + emb[e] @ a_rel^T
//   score[e] = sdot_s[src] + sdot_d[dst] + emb[e]·c     (c = a2 @ a_rel)
//   ee[e]    = exp(-leaky(score))
//   acc[n]   = sum_{e: src=n} ee*(xd[dst] + m_rel)  ;  rs[n] = sum ee
//   out[n]   = elu( xs[n] + acc[n]/rs[n] )
// ---------------------------------------------------------------------------

#define NMAX 50000
#define GAT_ALPHA 0.2f

__device__ float g_xsd[(size_t)NMAX * 256];   // [n][0:128]=xs, [n][128:256]=xd
__device__ float g_sdot[(size_t)NMAX * 2];
__device__ float g_u[320];                    // u_s, u_d, c
__device__ float g_rowsum[NMAX];

__device__ __forceinline__ void fma2(unsigned long long &acc,
                                     unsigned long long a, unsigned long long b) {
    asm("fma.rn.f32x2 %0, %1, %2, %0;" : "+l"(acc) : "l"(a), "l"(b));
}
__device__ __forceinline__ float2 unpack2(unsigned long long v) {
    float2 r;
    asm("mov.b64 {%0, %1}, %2;" : "=f"(r.x), "=f"(r.y) : "l"(v));
    return r;
}
__device__ __forceinline__ unsigned long long pack_dup(float w) {
    unsigned long long r;
    asm("mov.b64 %0, {%1, %1};" : "=l"(r) : "f"(w));
    return r;
}

// ---------------------------------------------------------------------------
__global__ void zero_kernel(float* __restrict__ h, int nh, int nr) {
    int stride = gridDim.x * blockDim.x;
    int i = blockIdx.x * blockDim.x + threadIdx.x;
    for (int j = i; j < nh; j += stride) h[j] = 0.f;
    for (int j = i; j < nr; j += stride) g_rowsum[j] = 0.f;
}

// ---------------------------------------------------------------------------
__global__ void vec_kernel(const float* __restrict__ a, const float* __restrict__ a2) {
    __shared__ float a2s[128];
    int t = threadIdx.x;
    if (t < 128) a2s[t] = a2[t];
    __syncthreads();
    if (t < 320) {
        float acc = 0.f;
        #pragma unroll 8
        for (int o = 0; o < 128; o++) acc += a2s[o] * a[o * 320 + t];
        g_u[t] = acc;
    }
}

// ---------------------------------------------------------------------------
// prep: xs/xd per-node GEMM + sdot fold. 16 nodes/block, 256 threads.
// ---------------------------------------------------------------------------
__global__ void __launch_bounds__(256) prep_kernel(const float* __restrict__ x,
                                                   const float* __restrict__ a, int N) {
    __shared__ float xs_sm[16 * 128];
    __shared__ float us_sm[256];
    int t = threadIdx.x;
    int n0 = blockIdx.x * 16;

    us_sm[t] = g_u[t];

    const float4* xg = (const float4*)(x + (size_t)n0 * 128);
    size_t lim4 = (size_t)N * 32;
    float4 z4 = make_float4(0.f, 0.f, 0.f, 0.f);
    ((float4*)xs_sm)[t]       = ((size_t)n0 * 32 + t       < lim4) ? xg[t]       : z4;
    ((float4*)xs_sm)[t + 256] = ((size_t)n0 * 32 + t + 256 < lim4) ? xg[t + 256] : z4;
    __syncthreads();

    const float* arow = (t < 128) ? (a + (size_t)t * 320)
                                  : (a + (size_t)(t - 128) * 320 + 128);
    unsigned long long acc[16];
    #pragma unroll
    for (int n = 0; n < 16; n++) acc[n] = 0ull;

    #pragma unroll 4
    for (int k4 = 0; k4 < 32; k4++) {
        ulonglong2 wv = ((const ulonglong2*)arow)[k4];
        #pragma unroll
        for (int n = 0; n < 16; n++) {
            ulonglong2 xv = ((const ulonglong2*)(xs_sm + n * 128))[k4];
            fma2(acc[n], xv.x, wv.x);
            fma2(acc[n], xv.y, wv.y);
        }
    }
    #pragma unroll
    for (int n = 0; n < 16; n++) {
        if (n0 + n < N) {
            float2 f = unpack2(acc[n]);
            g_xsd[(size_t)(n0 + n) * 256 + t] = f.x + f.y;
        }
    }

    // sdot fold: node n = t>>4, k-chunk kq = t&15
    int n = t >> 4, kq = t & 15;
    float ps = 0.f, pd = 0.f;
    #pragma unroll
    for (int j = 0; j < 8; j++) {
        float xv = xs_sm[n * 128 + kq * 8 + j];
        ps += xv * us_sm[kq * 8 + j];
        pd += xv * us_sm[128 + kq * 8 + j];
    }
    #pragma unroll
    for (int off = 8; off; off >>= 1) {
        ps += __shfl_xor_sync(0xffffffffu, ps, off);
        pd += __shfl_xor_sync(0xffffffffu, pd, off);
    }
    if (kq == 0 && n0 + n < N) {
        g_sdot[2 * (n0 + n)] = ps;
        g_sdot[2 * (n0 + n) + 1] = pd;
    }
}

// ---------------------------------------------------------------------------
// Edge kernel: 256 threads, tile = 64 edges x 128 outputs, full K=64 staged.
// Warp grid 2x4: warp w -> eb=(w&1)*32, ob=(w>>1)*32.
// Lane: esub=l>>3 (8-edge group), osub=l&7 (4-output group).
// ---------------------------------------------------------------------------

// dynamic smem layout (floats):
#define SM_W    0            // [64][128]  w_sm[k][o]
#define SM_EMB  8192         // [64][64]   emb_sm[k][e]
#define SM_C    12288        // [64]
#define SM_SS   12352        // [64]
#define SM_SD   12416        // [64]
#define SM_EE   12480        // [64]
#define SM_SRC  12544        // int[64]
#define SM_DST  12608        // int[64]
#define SM_FLOATS 12672
#define SMEM_EDGE_BYTES (SM_FLOATS * 4)

__device__ __forceinline__ void prefetch_emb64(
    long long t, const float* __restrict__ emb1, const float* __restrict__ emb2,
    long long E1, long long E, int tid, float4 r[4])
{
    int e_loc = tid >> 2, q = tid & 3;
    long long ge = t * 64 + e_loc;
    if (ge >= E) ge = E - 1;
    const float* ep = (ge < E1) ? (emb1 + ge * 64) : (emb2 + (ge - E1) * 64);
    #pragma unroll
    for (int j = 0; j < 4; j++)
        r[j] = __ldg((const float4*)(ep + j * 16 + q * 4));
}

__device__ __forceinline__ void sts_emb64(float* emb_sm, int tid, const float4 r[4]) {
    int e_loc = tid >> 2, q = tid & 3;
    #pragma unroll
    for (int j = 0; j < 4; j++) {
        int k = j * 16 + q * 4;
        emb_sm[(k + 0) * 64 + e_loc] = r[j].x;
        emb_sm[(k + 1) * 64 + e_loc] = r[j].y;
        emb_sm[(k + 2) * 64 + e_loc] = r[j].z;
        emb_sm[(k + 3) * 64 + e_loc] = r[j].w;
    }
}

__device__ __forceinline__ void prefetch_idx(
    long long t, const int* __restrict__ edge1, const int* __restrict__ edge2,
    long long E1, long long E2, long long E, int tid,
    int& ps, int& pd, float& pss, float& psd)
{
    ps = 0; pd = 0; pss = 0.f; psd = 0.f;
    if (tid < 64) {
        long long ge = t * 64 + tid;
        if (ge < E) {
            if (ge < E1) { ps = edge1[ge]; pd = edge1[E1 + ge]; }
            else { long long g2 = ge - E1; ps = edge2[g2]; pd = edge2[E2 + g2]; }
            pss = g_sdot[2 * ps];
            psd = g_sdot[2 * pd + 1];
        }
    }
}

__global__ void __launch_bounds__(256, 2) edge_kernel(
    const int* __restrict__ edge1, const float* __restrict__ emb1,
    const int* __restrict__ edge2, const float* __restrict__ emb2,
    const float* __restrict__ a, float* __restrict__ hout,
    int E1i, int E2i)
{
    extern __shared__ float smem[];
    float* w_sm   = smem + SM_W;
    float* emb_sm = smem + SM_EMB;
    float* c_sm   = smem + SM_C;
    float* ss_sm  = smem + SM_SS;
    float* sd_sm  = smem + SM_SD;
    float* ee_sm  = smem + SM_EE;
    int*   srcs   = (int*)(smem + SM_SRC);
    int*   dsts   = (int*)(smem + SM_DST);

    const long long E1 = E1i, E2 = E2i;
    const long long E = E1 + E2;
    const long long T = (E + 63) >> 6;

    int tid = threadIdx.x;
    int warp = tid >> 5, lane = tid & 31;
    int eb = (warp & 1) * 32, ob = (warp >> 1) * 32;
    int esub = lane >> 3, osub = lane & 7;
    int e0 = eb + esub * 8;          // lane's 8 edges: e0..e0+7
    int o0 = ob + osub * 4;          // lane's 4 outputs

    // stage weights [k][o] = a_rel[o][k]
    for (int i = tid; i < 8192; i += 256) {
        int o = i & 127, k = i >> 7;
        w_sm[k * 128 + o] = a[(size_t)o * 320 + 256 + k];
    }
    if (tid < 64) c_sm[tid] = g_u[256 + tid];

    long long t = blockIdx.x;
    const long long stride = gridDim.x;

    float4 rp[4];
    int ps, pd;
    float pss, psd;
    if (t < T) {
        prefetch_emb64(t, emb1, emb2, E1, E, tid, rp);
        prefetch_idx(t, edge1, edge2, E1, E2, E, tid, ps, pd, pss, psd);
    }
    __syncthreads();   // w_sm / c_sm ready

    for (; t < T; t += stride) {
        // ---- stage tile ----
        if (tid < 64) { srcs[tid] = ps; dsts[tid] = pd; ss_sm[tid] = pss; sd_sm[tid] = psd; }
        sts_emb64(emb_sm, tid, rp);
        __syncthreads();

        // prefetch next tile while GEMM runs
        if (t + stride < T) {
            prefetch_emb64(t + stride, emb1, emb2, E1, E, tid, rp);
            prefetch_idx(t + stride, edge1, edge2, E1, E2, E, tid, ps, pd, pss, psd);
        }

        // ---- GEMM: 64 edges x 128 outs x K64 ----
        unsigned long long acc[4][4];
        #pragma unroll
        for (int p = 0; p < 4; p++)
            #pragma unroll
            for (int j = 0; j < 4; j++) acc[p][j] = 0ull;

        #pragma unroll 8
        for (int k = 0; k < 64; k++) {
            const float* ep = emb_sm + k * 64 + e0;
            ulonglong2 P01 = *(const ulonglong2*)ep;
            ulonglong2 P23 = *(const ulonglong2*)(ep + 4);
            float4 wv = *(const float4*)&w_sm[k * 128 + o0];
            unsigned long long w0 = pack_dup(wv.x), w1 = pack_dup(wv.y);
            unsigned long long w2 = pack_dup(wv.z), w3 = pack_dup(wv.w);
            fma2(acc[0][0], P01.x, w0); fma2(acc[0][1], P01.x, w1);
            fma2(acc[0][2], P01.x, w2); fma2(acc[0][3], P01.x, w3);
            fma2(acc[1][0], P01.y, w0); fma2(acc[1][1], P01.y, w1);
            fma2(acc[1][2], P01.y, w2); fma2(acc[1][3], P01.y, w3);
            fma2(acc[2][0], P23.x, w0); fma2(acc[2][1], P23.x, w1);
            fma2(acc[2][2], P23.x, w2); fma2(acc[2][3], P23.x, w3);
            fma2(acc[3][0], P23.y, w0); fma2(acc[3][1], P23.y, w1);
            fma2(acc[3][2], P23.y, w2); fma2(acc[3][3], P23.y, w3);
        }

        // ---- score: warp w owns edges 8w..8w+7 ----
        {
            int e_sc = warp * 8 + (lane >> 2);
            int kq = lane & 3;
            float part = 0.f;
            #pragma unroll
            for (int i = 0; i < 16; i++) {
                int k = kq * 16 + i;
                part += emb_sm[k * 64 + e_sc] * c_sm[k];
            }
            part += __shfl_xor_sync(0xffffffffu, part, 1);
            part += __shfl_xor_sync(0xffffffffu, part, 2);
            if (kq == 0) {
                long long ge = t * 64 + e_sc;
                float eev = 0.f;
                if (ge < E) {
                    float sc = part + ss_sm[e_sc] + sd_sm[e_sc];
                    float pw = sc > 0.f ? sc : GAT_ALPHA * sc;
                    eev = __expf(-pw);
                    atomicAdd(&g_rowsum[srcs[e_sc]], eev);
                }
                ee_sm[e_sc] = eev;
            }
        }
        __syncthreads();   // ee ready for all warps

        // ---- epilogue: v = ee*(xd[dst] + m_rel) -> red to hout[src] ----
        #pragma unroll
        for (int i = 0; i < 8; i++) {
            int p = i >> 1, hh = i & 1;
            int ei = e0 + i;
            float eev = ee_sm[ei];
            int s = srcs[ei], d = dsts[ei];
            float2 m0 = unpack2(acc[p][0]);
            float2 m1 = unpack2(acc[p][1]);
            float2 m2 = unpack2(acc[p][2]);
            float2 m3 = unpack2(acc[p][3]);
            float4 xd = *(const float4*)&g_xsd[(size_t)d * 256 + 128 + o0];
            float v0 = eev * (xd.x + (hh ? m0.y : m0.x));
            float v1 = eev * (xd.y + (hh ? m1.y : m1.x));
            float v2 = eev * (xd.z + (hh ? m2.y : m2.x));
            float v3 = eev * (xd.w + (hh ? m3.y : m3.x));
            float* dp = hout + (size_t)s * 128 + o0;
            asm volatile("red.global.add.v4.f32 [%0], {%1, %2, %3, %4};"
                         :: "l"(dp), "f"(v0), "f"(v1), "f"(v2), "f"(v3) : "memory");
        }
        __syncthreads();   // srcs/dsts/ee consumed before next stage
    }
}

// ---------------------------------------------------------------------------
__global__ void final_kernel(float* __restrict__ hout, int N) {
    int total = N * 128;
    int stride = gridDim.x * blockDim.x;
    for (int i = blockIdx.x * blockDim.x + threadIdx.x; i < total; i += stride) {
        int n = i >> 7;
        float rs = g_rowsum[n];
        float v;
        if (rs > 0.f) {
            v = g_xsd[(size_t)n * 256 + (i & 127)] + hout[i] / rs;
        } else {
            v = 0.f;
        }
        hout[i] = v > 0.f ? v : expm1f(v);
    }
}

// ---------------------------------------------------------------------------
extern "C" void kernel_launch(void* const* d_in, const int* in_sizes, int n_in,
                              void* d_out, int out_size) {
    const float* x     = (const float*)d_in[0];
    const int*   edge1 = (const int*)  d_in[1];
    const float* emb1  = (const float*)d_in[2];
    const int*   edge2 = (const int*)  d_in[3];
    const float* emb2  = (const float*)d_in[4];
    const float* a     = (const float*)d_in[5];
    const float* a2    = (const float*)d_in[6];
    float* hout = (float*)d_out;

    int N  = in_sizes[0] / 128;
    int E1 = in_sizes[1] / 2;
    int E2 = in_sizes[3] / 2;

    cudaFuncSetAttribute(edge_kernel,
                         cudaFuncAttributeMaxDynamicSharedMemorySize, SMEM_EDGE_BYTES);

    zero_kernel<<<1024, 256>>>(hout, N * 128, N);
    vec_kernel<<<1, 320>>>(a, a2);
    prep_kernel<<<(N + 15) / 16, 256>>>(x, a, N);
    edge_kernel<<<296, 256, SMEM_EDGE_BYTES>>>(edge1, emb1, edge2, emb2, a, hout, E1, E2);
    final_kernel<<<1024, 256>>>(hout, N);
}

// round 5
// speedup vs baseline: 2.8838x; 1.2220x over previous
#include <cuda_runtime.h>
#include <cstdint>

// ---------------------------------------------------------------------------
// SpGraphAttentionLayer (GAT forward).  N=50000, D=128, O=128, R=64, E=1e6.
//
// Factored form (segment sums distribute over the linear maps):
//   u_s = a2 @ a_src, u_d = a2 @ a_dst, c = a2 @ a_rel
//   sdot_s[n] = x[n]·u_s ; sdot_d[n] = x[n]·u_d
//   score[e]  = sdot_s[src] + sdot_d[dst] + emb[e]·c
//   ee[e]     = exp(-leaky(score))
//   rs[n]     = Σ_{e:src=n} ee
//   w[n]      = Σ_{e:src=n} ee·emb[e]            (R^64)
//   y[n]      = Σ_{e:src=n} ee·x[dst]            (R^128)
//   out[n]    = rs>0 ? elu( [x[n], y[n]/rs, w[n]/rs] @ a^T ) : 0
// ---------------------------------------------------------------------------

#define NMAX 50000
#define GAT_ALPHA 0.2f

__device__ float g_sdot[(size_t)NMAX * 2];   // [2n]=sdot_s, [2n+1]=sdot_d
__device__ float g_u[320];                   // u_s, u_d, c
__device__ float g_rowsum[NMAX];
__device__ float g_w[(size_t)NMAX * 64];
__device__ float g_y[(size_t)NMAX * 128];

__device__ __forceinline__ void fma2(unsigned long long &acc,
                                     unsigned long long a, unsigned long long b) {
    asm("fma.rn.f32x2 %0, %1, %2, %0;" : "+l"(acc) : "l"(a), "l"(b));
}
__device__ __forceinline__ float2 unpack2(unsigned long long v) {
    float2 r;
    asm("mov.b64 {%0, %1}, %2;" : "=f"(r.x), "=f"(r.y) : "l"(v));
    return r;
}

// ---------------------------------------------------------------------------
// Zero the scatter accumulators.
// ---------------------------------------------------------------------------
__global__ void zero_kernel(int N) {
    int stride = gridDim.x * blockDim.x;
    int i = blockIdx.x * blockDim.x + threadIdx.x;
    int nw = N * 16;   // float4 count in g_w
    int ny = N * 32;   // float4 count in g_y
    float4 z = make_float4(0.f, 0.f, 0.f, 0.f);
    for (int j = i; j < nw; j += stride) ((float4*)g_w)[j] = z;
    for (int j = i; j < ny; j += stride) ((float4*)g_y)[j] = z;
    for (int j = i; j < N; j += stride) g_rowsum[j] = 0.f;
}

// ---------------------------------------------------------------------------
// u vectors: u[t] = sum_o a2[o] * a[o][t],  t in [0,320)
// ---------------------------------------------------------------------------
__global__ void vec_kernel(const float* __restrict__ a, const float* __restrict__ a2) {
    __shared__ float a2s[128];
    int t = threadIdx.x;
    if (t < 128) a2s[t] = a2[t];
    __syncthreads();
    if (t < 320) {
        float acc = 0.f;
        #pragma unroll 8
        for (int o = 0; o < 128; o++) acc += a2s[o] * a[o * 320 + t];
        g_u[t] = acc;
    }
}

// ---------------------------------------------------------------------------
// sdot_s[n] = x[n]·u_s ; sdot_d[n] = x[n]·u_d.  One warp per node.
// ---------------------------------------------------------------------------
__global__ void __launch_bounds__(128) sdot_kernel(const float* __restrict__ x, int N) {
    __shared__ float us[256];
    int t = threadIdx.x;
    us[t] = g_u[t];
    us[t + 128] = g_u[t + 128];
    __syncthreads();

    int n = blockIdx.x * 4 + (t >> 5);
    if (n >= N) return;
    int lane = t & 31;
    float ps = 0.f, pd = 0.f;
    #pragma unroll
    for (int j = 0; j < 4; j++) {
        float xv = x[(size_t)n * 128 + lane + 32 * j];
        ps += xv * us[lane + 32 * j];
        pd += xv * us[128 + lane + 32 * j];
    }
    #pragma unroll
    for (int off = 16; off; off >>= 1) {
        ps += __shfl_xor_sync(0xffffffffu, ps, off);
        pd += __shfl_xor_sync(0xffffffffu, pd, off);
    }
    if (lane == 0) { g_sdot[2 * n] = ps; g_sdot[2 * n + 1] = pd; }
}

// ---------------------------------------------------------------------------
// Edge kernel: one warp processes 32 edges per chunk. Per edge:
//   score dot (emb·c via butterfly), ee, then scatter:
//     rs[src] += ee ; w[src] += ee*emb ; y[src] += ee*x[dst]
// ---------------------------------------------------------------------------
__global__ void __launch_bounds__(256) edge_kernel(
    const int* __restrict__ edge1, const float* __restrict__ emb1,
    const int* __restrict__ edge2, const float* __restrict__ emb2,
    const float* __restrict__ x, int E1i, int E2i)
{
    const long long E1 = E1i, E2 = E2i;
    const long long E = E1 + E2;
    const long long CH = (E + 31) >> 5;

    const int lane = threadIdx.x & 31;
    long long gwarp = (long long)blockIdx.x * (blockDim.x >> 5) + (threadIdx.x >> 5);
    const long long nwarps = (long long)gridDim.x * (blockDim.x >> 5);

    const float2 c2 = ((const float2*)(g_u + 256))[lane];

    for (long long ch = gwarp; ch < CH; ch += nwarps) {
        const long long base = ch << 5;

        // per-lane edge metadata for this 32-edge chunk
        long long ge = base + lane;
        int s = 0, d = 0;
        float ss = 0.f, sd = 0.f;
        if (ge < E) {
            if (ge < E1) { s = edge1[ge]; d = edge1[E1 + ge]; }
            else { long long g2 = ge - E1; s = edge2[g2]; d = edge2[E2 + g2]; }
            ss = g_sdot[2 * s];
            sd = g_sdot[2 * d + 1];
        }
        int cnt = (int)((E - base < 32) ? (E - base) : 32);

        #pragma unroll 4
        for (int i = 0; i < cnt; i++) {
            long long e = base + i;
            const float* ep = (e < E1) ? (emb1 + e * 64) : (emb2 + (e - E1) * 64);
            float2 em = ((const float2*)ep)[lane];

            // score = emb·c + sdot_s[src] + sdot_d[dst]
            float p = em.x * c2.x + em.y * c2.y;
            p += __shfl_xor_sync(0xffffffffu, p, 1);
            p += __shfl_xor_sync(0xffffffffu, p, 2);
            p += __shfl_xor_sync(0xffffffffu, p, 4);
            p += __shfl_xor_sync(0xffffffffu, p, 8);
            p += __shfl_xor_sync(0xffffffffu, p, 16);
            float sc = p + __shfl_sync(0xffffffffu, ss, i)
                         + __shfl_sync(0xffffffffu, sd, i);
            float pw = sc > 0.f ? sc : GAT_ALPHA * sc;
            float ee = __expf(-pw);

            int si = __shfl_sync(0xffffffffu, s, i);
            int di = __shfl_sync(0xffffffffu, d, i);

            // w[src] += ee*emb   (lane covers 2 consecutive floats)
            float w0 = ee * em.x, w1 = ee * em.y;
            float* wp = g_w + (size_t)si * 64 + lane * 2;
            asm volatile("red.global.add.v2.f32 [%0], {%1, %2};"
                         :: "l"(wp), "f"(w0), "f"(w1) : "memory");

            // y[src] += ee*x[dst]   (lane covers 4 consecutive floats)
            float4 xv = __ldg((const float4*)(x + (size_t)di * 128) + lane);
            float v0 = ee * xv.x, v1 = ee * xv.y, v2 = ee * xv.z, v3 = ee * xv.w;
            float* yp = g_y + (size_t)si * 128 + lane * 4;
            asm volatile("red.global.add.v4.f32 [%0], {%1, %2, %3, %4};"
                         :: "l"(yp), "f"(v0), "f"(v1), "f"(v2), "f"(v3) : "memory");

            if (lane == i) atomicAdd(&g_rowsum[si], ee);
        }
    }
}

// ---------------------------------------------------------------------------
// Final node GEMM: out[n][o] = elu( z[n] · a[o] ), z = [x, y/rs, w/rs] (320)
// 16 nodes per block, 256 threads: col = t&127, group = t>>7 handles 8 nodes.
// ---------------------------------------------------------------------------
__global__ void __launch_bounds__(256) final_kernel(
    const float* __restrict__ x, const float* __restrict__ a,
    float* __restrict__ out, int N)
{
    __shared__ float z_sm[16 * 320];
    __shared__ float inv_sm[16];
    __shared__ int   ok_sm[16];

    int t = threadIdx.x;
    int n0 = blockIdx.x * 16;

    if (t < 16) {
        float rs = (n0 + t < N) ? g_rowsum[n0 + t] : 0.f;
        ok_sm[t]  = rs > 0.f;
        inv_sm[t] = rs > 0.f ? 1.f / rs : 0.f;
    }
    __syncthreads();

    // stage z = [x | y*inv | w*inv], guarded
    float4 z4 = make_float4(0.f, 0.f, 0.f, 0.f);
    #pragma unroll
    for (int it = 0; it < 2; it++) {                  // x: 16*32 float4
        int idx = t + it * 256;
        int n = idx >> 5, q = idx & 31;
        float4 v = (n0 + n < N) ? __ldg((const float4*)(x + (size_t)(n0 + n) * 128) + q) : z4;
        *(float4*)&z_sm[n * 320 + q * 4] = v;
    }
    #pragma unroll
    for (int it = 0; it < 2; it++) {                  // y: 16*32 float4
        int idx = t + it * 256;
        int n = idx >> 5, q = idx & 31;
        float4 v = (n0 + n < N) ? ((const float4*)(g_y + (size_t)(n0 + n) * 128))[q] : z4;
        float iv = inv_sm[n];
        v.x *= iv; v.y *= iv; v.z *= iv; v.w *= iv;
        *(float4*)&z_sm[n * 320 + 128 + q * 4] = v;
    }
    {                                                  // w: 16*16 float4
        int idx = t;
        if (idx < 256) {
            int n = idx >> 4, q = idx & 15;
            float4 v = (n0 + n < N) ? ((const float4*)(g_w + (size_t)(n0 + n) * 64))[q] : z4;
            float iv = inv_sm[n];
            v.x *= iv; v.y *= iv; v.z *= iv; v.w *= iv;
            *(float4*)&z_sm[n * 320 + 256 + q * 4] = v;
        }
    }
    __syncthreads();

    int col = t & 127;
    int grp = t >> 7;                 // nodes grp, grp+2, ..., grp+14
    const float* arow = a + (size_t)col * 320;

    unsigned long long acc[8];
    #pragma unroll
    for (int j = 0; j < 8; j++) acc[j] = 0ull;

    #pragma unroll 4
    for (int k4 = 0; k4 < 80; k4++) {
        ulonglong2 wv = ((const ulonglong2*)arow)[k4];
        #pragma unroll
        for (int j = 0; j < 8; j++) {
            int n = grp + 2 * j;
            ulonglong2 zv = ((const ulonglong2*)(z_sm + n * 320))[k4];
            fma2(acc[j], zv.x, wv.x);
            fma2(acc[j], zv.y, wv.y);
        }
    }

    #pragma unroll
    for (int j = 0; j < 8; j++) {
        int n = grp + 2 * j;
        if (n0 + n < N) {
            float2 f = unpack2(acc[j]);
            float v = f.x + f.y;
            v = ok_sm[n] ? (v > 0.f ? v : expm1f(v)) : 0.f;
            out[(size_t)(n0 + n) * 128 + col] = v;
        }
    }
}

// ---------------------------------------------------------------------------
extern "C" void kernel_launch(void* const* d_in, const int* in_sizes, int n_in,
                              void* d_out, int out_size) {
    const float* x     = (const float*)d_in[0];
    const int*   edge1 = (const int*)  d_in[1];
    const float* emb1  = (const float*)d_in[2];
    const int*   edge2 = (const int*)  d_in[3];
    const float* emb2  = (const float*)d_in[4];
    const float* a     = (const float*)d_in[5];
    const float* a2    = (const float*)d_in[6];
    float* out = (float*)d_out;

    int N  = in_sizes[0] / 128;
    int E1 = in_sizes[1] / 2;
    int E2 = in_sizes[3] / 2;

    zero_kernel<<<1024, 256>>>(N);
    vec_kernel<<<1, 320>>>(a, a2);
    sdot_kernel<<<(N + 3) / 4, 128>>>(x, N);
    edge_kernel<<<888, 256>>>(edge1, emb1, edge2, emb2, x, E1, E2);
    final_kernel<<<(N + 15) / 16, 256>>>(x, a, out, N);
}

// round 6
// speedup vs baseline: 3.7542x; 1.3018x over previous
#include <cuda_runtime.h>
#include <cstdint>

// ---------------------------------------------------------------------------
// SpGraphAttentionLayer (GAT forward).  N=50000, D=128, O=128, R=64, E=1e6.
//
// Factored form (segment sums distribute over the linear maps):
//   u = a2 @ a  (320)   ; c = u[256:320]
//   sdot_s[n] = x[n]·u[0:128] ; sdot_d[n] = x[n]·u[128:256]
//   score[e]  = sdot_s[src] + sdot_d[dst] + emb[e]·c
//   ee[e]     = exp(-leaky(score))
//   rs[n]     = Σ_{e:src=n} ee
//   w[n]      = Σ_{e:src=n} ee·emb[e]            (R^64)
//   y[n]      = Σ_{e:src=n} ee·x[dst]            (R^128)
//   out[n]    = rs>0 ? elu( [x[n], y[n]/rs, w[n]/rs] @ a^T ) : 0
// ---------------------------------------------------------------------------

#define NMAX 50000
#define GAT_ALPHA 0.2f

__device__ float g_sdot[(size_t)NMAX * 2];
__device__ float g_u[320];
__device__ float g_rowsum[NMAX];
__device__ float g_w[(size_t)NMAX * 64];
__device__ float g_y[(size_t)NMAX * 128];
__device__ float g_aT[320 * 128];          // a transposed: [k][o]

__device__ __forceinline__ void fma2(unsigned long long &acc,
                                     unsigned long long a, unsigned long long b) {
    asm("fma.rn.f32x2 %0, %1, %2, %0;" : "+l"(acc) : "l"(a), "l"(b));
}
__device__ __forceinline__ float2 unpack2(unsigned long long v) {
    float2 r;
    asm("mov.b64 {%0, %1}, %2;" : "=f"(r.x), "=f"(r.y) : "l"(v));
    return r;
}

// ---------------------------------------------------------------------------
__global__ void zero_kernel(int N) {
    int stride = gridDim.x * blockDim.x;
    int i = blockIdx.x * blockDim.x + threadIdx.x;
    int nw = N * 16, ny = N * 32;
    float4 z = make_float4(0.f, 0.f, 0.f, 0.f);
    for (int j = i; j < nw; j += stride) ((float4*)g_w)[j] = z;
    for (int j = i; j < ny; j += stride) ((float4*)g_y)[j] = z;
    for (int j = i; j < N; j += stride) g_rowsum[j] = 0.f;
}

// ---------------------------------------------------------------------------
__global__ void vec_kernel(const float* __restrict__ a, const float* __restrict__ a2) {
    __shared__ float a2s[128];
    int t = threadIdx.x;
    if (t < 128) a2s[t] = a2[t];
    __syncthreads();
    if (t < 320) {
        float acc = 0.f;
        #pragma unroll 8
        for (int o = 0; o < 128; o++) acc += a2s[o] * a[o * 320 + t];
        g_u[t] = acc;
    }
}

// ---------------------------------------------------------------------------
// a_T[k][o] = a[o][k]  (160 KB, one-time)
// ---------------------------------------------------------------------------
__global__ void transpose_a_kernel(const float* __restrict__ a) {
    int idx = blockIdx.x * 256 + threadIdx.x;
    if (idx < 320 * 128) {
        int k = idx >> 7, o = idx & 127;
        g_aT[idx] = a[o * 320 + k];
    }
}

// ---------------------------------------------------------------------------
__global__ void __launch_bounds__(128) sdot_kernel(const float* __restrict__ x, int N) {
    __shared__ float us[256];
    int t = threadIdx.x;
    us[t] = g_u[t];
    us[t + 128] = g_u[t + 128];
    __syncthreads();

    int n = blockIdx.x * 4 + (t >> 5);
    if (n >= N) return;
    int lane = t & 31;
    float ps = 0.f, pd = 0.f;
    #pragma unroll
    for (int j = 0; j < 4; j++) {
        float xv = x[(size_t)n * 128 + lane + 32 * j];
        ps += xv * us[lane + 32 * j];
        pd += xv * us[128 + lane + 32 * j];
    }
    #pragma unroll
    for (int off = 16; off; off >>= 1) {
        ps += __shfl_xor_sync(0xffffffffu, ps, off);
        pd += __shfl_xor_sync(0xffffffffu, pd, off);
    }
    if (lane == 0) { g_sdot[2 * n] = ps; g_sdot[2 * n + 1] = pd; }
}

// ---------------------------------------------------------------------------
// Edge kernel: tiles of 128 edges, 256 threads.
//  - emb staged straight [e][64] (coalesced both sides)
//  - score dot computed from in-flight staging registers (half-warp reduce)
//  - scatter: warp handles 16 edges in 2 batches of 8 (MLP=8 on x-gather)
// ---------------------------------------------------------------------------
__global__ void __launch_bounds__(256, 2) edge_kernel(
    const int* __restrict__ edge1, const float* __restrict__ emb1,
    const int* __restrict__ edge2, const float* __restrict__ emb2,
    const float* __restrict__ x, int E1i, int E2i)
{
    __shared__ float emb_sm[128 * 64];
    __shared__ float sc_sm[128], ss_sm[128], sd_sm[128], ee_sm[128];
    __shared__ int   src_sm[128], dst_sm[128];

    const long long E1 = E1i, E2 = E2i;
    const long long E = E1 + E2;
    const long long T = (E + 127) >> 7;

    const int tid = threadIdx.x;
    const int warp = tid >> 5, lane = tid & 31;
    const int q = tid & 15;
    const float4 c4 = *(const float4*)(g_u + 256 + q * 4);

    for (long long t = blockIdx.x; t < T; t += gridDim.x) {
        const long long base = t << 7;

        // ---- index/sdot staging ----
        if (tid < 128) {
            long long ge = base + tid;
            int s = 0, d = 0;
            float ss = 0.f, sd = 0.f;
            if (ge < E) {
                if (ge < E1) { s = edge1[ge]; d = edge1[E1 + ge]; }
                else { long long g2 = ge - E1; s = edge2[g2]; d = edge2[E2 + g2]; }
                ss = g_sdot[2 * s];
                sd = g_sdot[2 * d + 1];
            }
            src_sm[tid] = s; dst_sm[tid] = d; ss_sm[tid] = ss; sd_sm[tid] = sd;
        }

        // ---- emb staging + score partials ----
        #pragma unroll
        for (int j = 0; j < 8; j++) {
            int idx = tid + j * 256;          // 0..2047
            int e = idx >> 4;
            long long ge = base + e;
            if (ge >= E) ge = E - 1;
            const float* ep = (ge < E1) ? (emb1 + ge * 64) : (emb2 + (ge - E1) * 64);
            float4 v = __ldg((const float4*)ep + q);
            *(float4*)&emb_sm[idx * 4] = v;
            float p = v.x * c4.x + v.y * c4.y + v.z * c4.z + v.w * c4.w;
            p += __shfl_xor_sync(0xffffffffu, p, 1);
            p += __shfl_xor_sync(0xffffffffu, p, 2);
            p += __shfl_xor_sync(0xffffffffu, p, 4);
            p += __shfl_xor_sync(0xffffffffu, p, 8);
            if ((lane & 15) == 0) sc_sm[e] = p;
        }
        __syncthreads();

        // ---- softmax weight + rowsum ----
        if (tid < 128) {
            long long ge = base + tid;
            float ee = 0.f;
            if (ge < E) {
                float sc = sc_sm[tid] + ss_sm[tid] + sd_sm[tid];
                float pw = sc > 0.f ? sc : GAT_ALPHA * sc;
                ee = __expf(-pw);
                atomicAdd(&g_rowsum[src_sm[tid]], ee);
            }
            ee_sm[tid] = ee;
        }
        __syncthreads();

        // ---- scatter: warp owns edges warp*16..+15, batches of 8 ----
        #pragma unroll
        for (int b = 0; b < 2; b++) {
            int e0 = warp * 16 + b * 8;
            float eev[8]; int si[8];
            float4 xv[8]; float2 em[8];
            #pragma unroll
            for (int i = 0; i < 8; i++) {
                int e = e0 + i;
                eev[i] = ee_sm[e];
                si[i] = src_sm[e];
                int di = dst_sm[e];
                xv[i] = __ldg((const float4*)(x + (size_t)di * 128) + lane);
                em[i] = *(const float2*)&emb_sm[e * 64 + lane * 2];
            }
            #pragma unroll
            for (int i = 0; i < 8; i++) {
                if (eev[i] != 0.f) {
                    float w0 = eev[i] * em[i].x, w1 = eev[i] * em[i].y;
                    float* wp = g_w + (size_t)si[i] * 64 + lane * 2;
                    asm volatile("red.global.add.v2.f32 [%0], {%1, %2};"
                                 :: "l"(wp), "f"(w0), "f"(w1) : "memory");
                    float v0 = eev[i] * xv[i].x, v1 = eev[i] * xv[i].y;
                    float v2 = eev[i] * xv[i].z, v3 = eev[i] * xv[i].w;
                    float* yp = g_y + (size_t)si[i] * 128 + lane * 4;
                    asm volatile("red.global.add.v4.f32 [%0], {%1, %2, %3, %4};"
                                 :: "l"(yp), "f"(v0), "f"(v1), "f"(v2), "f"(v3) : "memory");
                }
            }
        }
        __syncthreads();
    }
}

// ---------------------------------------------------------------------------
// Final GEMM: out[64n x 128o] = elu( z @ a^T ), z = [x | y/rs | w/rs] (K=320).
// 256 threads. Warp tile 16 nodes x 64 cols (8 warps = 4 x 2).
// Lane: nsub=lane>>3 (4 nodes), osub=lane&7 (8 cols as 4 f32x2 pairs).
// z staged pre-duplicated {v,v} pitch 65 (conflict-free LDS.64);
// a staged from g_aT straight, pitch 132 (16B-aligned, conflict-free LDS.128).
// ---------------------------------------------------------------------------
__global__ void __launch_bounds__(256) final_kernel(
    const float* __restrict__ x, float* __restrict__ out, int N)
{
    __shared__ float2 z_sm[64 * 65];      // [n][k] duplicated pairs
    __shared__ float  a_sm[64 * 132];     // [k][o]
    __shared__ float  inv_sm[64];

    const int tid = threadIdx.x;
    const int warp = tid >> 5, lane = tid & 31;
    const int n0 = blockIdx.x * 64;

    const int ob = (warp & 1) * 64;
    const int nb = (warp >> 1) * 16;
    const int nloc = nb + (lane >> 3) * 4;      // 4 nodes: nloc..nloc+3
    const int o0 = ob + (lane & 7) * 8;         // 8 cols:  o0..o0+7

    if (tid < 64) {
        float rs = (n0 + tid < N) ? g_rowsum[n0 + tid] : 0.f;
        inv_sm[tid] = rs > 0.f ? 1.f / rs : 0.f;
    }

    unsigned long long acc[4][4];
    #pragma unroll
    for (int j = 0; j < 4; j++)
        #pragma unroll
        for (int p = 0; p < 4; p++) acc[j][p] = 0ull;

    #pragma unroll
    for (int kc = 0; kc < 5; kc++) {
        __syncthreads();
        // stage a chunk [64k][128o] from g_aT (coalesced)
        #pragma unroll
        for (int it = 0; it < 8; it++) {
            int i = tid + it * 256;               // 0..2047 float4s
            int k = i >> 5, qq = i & 31;
            float4 av = *(const float4*)(g_aT + (size_t)(kc * 64 + k) * 128 + qq * 4);
            *(float4*)&a_sm[k * 132 + qq * 4] = av;
        }
        // stage z chunk (scalar, coalesced along k), duplicated
        #pragma unroll
        for (int it = 0; it < 16; it++) {
            int i = tid + it * 256;               // 0..4095
            int n = i >> 6, k = i & 63;
            float val = 0.f;
            if (n0 + n < N) {
                if (kc < 2)       val = x[(size_t)(n0 + n) * 128 + kc * 64 + k];
                else if (kc < 4)  val = g_y[(size_t)(n0 + n) * 128 + (kc - 2) * 64 + k] * inv_sm[n];
                else              val = g_w[(size_t)(n0 + n) * 64 + k] * inv_sm[n];
            }
            z_sm[n * 65 + k] = make_float2(val, val);
        }
        __syncthreads();

        #pragma unroll 8
        for (int k = 0; k < 64; k++) {
            ulonglong2 A01 = *(const ulonglong2*)&a_sm[k * 132 + o0];
            ulonglong2 A23 = *(const ulonglong2*)&a_sm[k * 132 + o0 + 4];
            #pragma unroll
            for (int j = 0; j < 4; j++) {
                unsigned long long zd = *(const unsigned long long*)&z_sm[(nloc + j) * 65 + k];
                fma2(acc[j][0], zd, A01.x);
                fma2(acc[j][1], zd, A01.y);
                fma2(acc[j][2], zd, A23.x);
                fma2(acc[j][3], zd, A23.y);
            }
        }
    }

    // epilogue
    #pragma unroll
    for (int j = 0; j < 4; j++) {
        int n = n0 + nloc + j;
        if (n < N) {
            bool ok = inv_sm[nloc + j] > 0.f;
            float o[8];
            #pragma unroll
            for (int p = 0; p < 4; p++) {
                float2 f = unpack2(acc[j][p]);
                o[2 * p] = f.x; o[2 * p + 1] = f.y;
            }
            #pragma unroll
            for (int q = 0; q < 8; q++)
                o[q] = ok ? (o[q] > 0.f ? o[q] : expm1f(o[q])) : 0.f;
            float* dp = out + (size_t)n * 128 + o0;
            *(float4*)dp = make_float4(o[0], o[1], o[2], o[3]);
            *(float4*)(dp + 4) = make_float4(o[4], o[5], o[6], o[7]);
        }
    }
}

// ---------------------------------------------------------------------------
extern "C" void kernel_launch(void* const* d_in, const int* in_sizes, int n_in,
                              void* d_out, int out_size) {
    const float* x     = (const float*)d_in[0];
    const int*   edge1 = (const int*)  d_in[1];
    const float* emb1  = (const float*)d_in[2];
    const int*   edge2 = (const int*)  d_in[3];
    const float* emb2  = (const float*)d_in[4];
    const float* a     = (const float*)d_in[5];
    const float* a2    = (const float*)d_in[6];
    float* out = (float*)d_out;

    int N  = in_sizes[0] / 128;
    int E1 = in_sizes[1] / 2;
    int E2 = in_sizes[3] / 2;

    zero_kernel<<<1024, 256>>>(N);
    vec_kernel<<<1, 320>>>(a, a2);
    transpose_a_kernel<<<160, 256>>>(a);
    sdot_kernel<<<(N + 3) / 4, 128>>>(x, N);
    edge_kernel<<<592, 256>>>(edge1, emb1, edge2, emb2, x, E1, E2);
    final_kernel<<<(N + 63) / 64, 256>>>(x, out, N);
}

// round 7
// speedup vs baseline: 4.0231x; 1.0716x over previous
#include <cuda_runtime.h>
#include <cstdint>

// ---------------------------------------------------------------------------
// SpGraphAttentionLayer (GAT forward).  N=50000, D=128, O=128, R=64, E=1e6.
//
// Factored form (segment sums distribute over the linear maps):
//   u = a2 @ a  (320)   ; c = u[256:320]
//   sdot_s[n] = x[n]·u[0:128] ; sdot_d[n] = x[n]·u[128:256]
//   score[e]  = sdot_s[src] + sdot_d[dst] + emb[e]·c
//   ee[e]     = exp(-leaky(score))
//   rs[n]     = Σ_{e:src=n} ee
//   w[n]      = Σ_{e:src=n} ee·emb[e]            (R^64)
//   y[n]      = Σ_{e:src=n} ee·x[dst]            (R^128)
//   out[n]    = rs>0 ? elu( [x[n], y[n]/rs, w[n]/rs] @ a^T ) : 0
// ---------------------------------------------------------------------------

#define NMAX 50000
#define GAT_ALPHA 0.2f

__device__ float g_sdot[(size_t)NMAX * 2];
__device__ float g_u[320];
__device__ float g_rowsum[NMAX];
__device__ float g_w[(size_t)NMAX * 64];
__device__ float g_y[(size_t)NMAX * 128];
__device__ float g_aT[320 * 128];          // a transposed: [k][o]

__device__ __forceinline__ void fma2(unsigned long long &acc,
                                     unsigned long long a, unsigned long long b) {
    asm("fma.rn.f32x2 %0, %1, %2, %0;" : "+l"(acc) : "l"(a), "l"(b));
}
__device__ __forceinline__ float2 unpack2(unsigned long long v) {
    float2 r;
    asm("mov.b64 {%0, %1}, %2;" : "=f"(r.x), "=f"(r.y) : "l"(v));
    return r;
}

// ---------------------------------------------------------------------------
__global__ void zero_kernel(int N) {
    int stride = gridDim.x * blockDim.x;
    int i = blockIdx.x * blockDim.x + threadIdx.x;
    int nw = N * 16, ny = N * 32;
    float4 z = make_float4(0.f, 0.f, 0.f, 0.f);
    for (int j = i; j < nw; j += stride) ((float4*)g_w)[j] = z;
    for (int j = i; j < ny; j += stride) ((float4*)g_y)[j] = z;
    for (int j = i; j < N; j += stride) g_rowsum[j] = 0.f;
}

// ---------------------------------------------------------------------------
__global__ void vec_kernel(const float* __restrict__ a, const float* __restrict__ a2) {
    __shared__ float a2s[128];
    int t = threadIdx.x;
    if (t < 128) a2s[t] = a2[t];
    __syncthreads();
    if (t < 320) {
        float acc = 0.f;
        #pragma unroll 8
        for (int o = 0; o < 128; o++) acc += a2s[o] * a[o * 320 + t];
        g_u[t] = acc;
    }
}

// ---------------------------------------------------------------------------
__global__ void transpose_a_kernel(const float* __restrict__ a) {
    int idx = blockIdx.x * 256 + threadIdx.x;
    if (idx < 320 * 128) {
        int k = idx >> 7, o = idx & 127;
        g_aT[idx] = a[o * 320 + k];
    }
}

// ---------------------------------------------------------------------------
__global__ void __launch_bounds__(128) sdot_kernel(const float* __restrict__ x, int N) {
    __shared__ float us[256];
    int t = threadIdx.x;
    us[t] = g_u[t];
    us[t + 128] = g_u[t + 128];
    __syncthreads();

    int n = blockIdx.x * 4 + (t >> 5);
    if (n >= N) return;
    int lane = t & 31;
    float ps = 0.f, pd = 0.f;
    #pragma unroll
    for (int j = 0; j < 4; j++) {
        float xv = x[(size_t)n * 128 + lane + 32 * j];
        ps += xv * us[lane + 32 * j];
        pd += xv * us[128 + lane + 32 * j];
    }
    #pragma unroll
    for (int off = 16; off; off >>= 1) {
        ps += __shfl_xor_sync(0xffffffffu, ps, off);
        pd += __shfl_xor_sync(0xffffffffu, pd, off);
    }
    if (lane == 0) { g_sdot[2 * n] = ps; g_sdot[2 * n + 1] = pd; }
}

// ---------------------------------------------------------------------------
// Edge kernel: fully register-resident, no smem, no block syncs.
// Warp owns 16 edges per chunk. Half-warp h handles edges 2i+h in phase i:
//   lane sub (=lane&15) holds emb[edge][4sub:4sub+4] in a register (em[i]).
// Score 64-dot reduces with 4 xor-shuffles inside the half-warp.
// Scatter per phase (2 edges): 1 red.v4 (w, per-lane addr across halves),
//   2 LDG.128 x-gather + 2 red.v4 (y), ee/src/dst via shuffles.
// Tail is branch-free: clamped indices, ee=0 => reds add zeros.
// ---------------------------------------------------------------------------
__global__ void __launch_bounds__(256) edge_kernel(
    const int* __restrict__ edge1, const float* __restrict__ emb1,
    const int* __restrict__ edge2, const float* __restrict__ emb2,
    const float* __restrict__ x, int E1i, int E2i)
{
    const long long E1 = E1i, E2 = E2i;
    const long long E = E1 + E2;
    const long long CH = (E + 15) >> 4;

    const int lane = threadIdx.x & 31;
    const int sub  = lane & 15;
    const int half = lane >> 4;

    long long gwarp = (long long)blockIdx.x * (blockDim.x >> 5) + (threadIdx.x >> 5);
    const long long nwarps = (long long)gridDim.x * (blockDim.x >> 5);

    const float4 c4 = *(const float4*)(g_u + 256 + sub * 4);

    for (long long ch = gwarp; ch < CH; ch += nwarps) {
        const long long base = ch << 4;

        // ---- per-edge metadata: lane j (both halves, el=lane&15) = edge base+el
        long long ge = base + sub;
        long long gec = (ge < E) ? ge : (E - 1);
        int s, d;
        if (gec < E1) { s = edge1[gec]; d = edge1[E1 + gec]; }
        else { long long g2 = gec - E1; s = edge2[g2]; d = edge2[E2 + g2]; }
        float ssd = g_sdot[2 * s] + g_sdot[2 * d + 1];

        // ---- stage emb into registers + score partials ----
        float4 em[8];
        float sc_mine = 0.f;
        #pragma unroll
        for (int i = 0; i < 8; i++) {
            long long e = base + 2 * i + half;
            if (e >= E) e = E - 1;
            const float* ep = (e < E1) ? (emb1 + e * 64) : (emb2 + (e - E1) * 64);
            em[i] = __ldg((const float4*)ep + sub);
            float p = em[i].x * c4.x + em[i].y * c4.y + em[i].z * c4.z + em[i].w * c4.w;
            p += __shfl_xor_sync(0xffffffffu, p, 1);
            p += __shfl_xor_sync(0xffffffffu, p, 2);
            p += __shfl_xor_sync(0xffffffffu, p, 4);
            p += __shfl_xor_sync(0xffffffffu, p, 8);
            // edge 2i   -> lane 2i   (from lane 0)
            // edge 2i+1 -> lane 2i+1 (from lane 16)
            float s0 = __shfl_sync(0xffffffffu, p, 0);
            float s1 = __shfl_sync(0xffffffffu, p, 16);
            if (lane == 2 * i)     sc_mine = s0;
            if (lane == 2 * i + 1) sc_mine = s1;
        }

        // ---- softmax weight on lanes 0..15 ----
        float ee = 0.f;
        if (lane < 16 && ge < E) {
            float sc = sc_mine + ssd;
            float pw = sc > 0.f ? sc : GAT_ALPHA * sc;
            ee = __expf(-pw);
            atomicAdd(&g_rowsum[s], ee);      // @P red.global.add, per-lane addr
        }

        // ---- scatter: phase i handles edges 2i (half 0) and 2i+1 (half 1) ----
        #pragma unroll
        for (int i = 0; i < 8; i++) {
            int j = 2 * i + half;
            float eej = __shfl_sync(0xffffffffu, ee, j);
            int   sij = __shfl_sync(0xffffffffu, s, j);
            int   dij = __shfl_sync(0xffffffffu, d, j);

            // w[src] += ee*emb  (16 lanes per half, distinct src per half)
            float w0 = eej * em[i].x, w1 = eej * em[i].y;
            float w2 = eej * em[i].z, w3 = eej * em[i].w;
            float* wp = g_w + (size_t)sij * 64 + sub * 4;
            asm volatile("red.global.add.v4.f32 [%0], {%1, %2, %3, %4};"
                         :: "l"(wp), "f"(w0), "f"(w1), "f"(w2), "f"(w3) : "memory");

            // y[src] += ee*x[dst]  (half covers 128 floats in 2 v4 slabs)
            const float4* xp = (const float4*)(x + (size_t)dij * 128);
            float4 x0 = __ldg(xp + sub);
            float4 x1 = __ldg(xp + sub + 16);
            float* yp = g_y + (size_t)sij * 128;
            float v0 = eej * x0.x, v1 = eej * x0.y, v2 = eej * x0.z, v3 = eej * x0.w;
            asm volatile("red.global.add.v4.f32 [%0], {%1, %2, %3, %4};"
                         :: "l"(yp + sub * 4), "f"(v0), "f"(v1), "f"(v2), "f"(v3) : "memory");
            float u0 = eej * x1.x, u1 = eej * x1.y, u2 = eej * x1.z, u3 = eej * x1.w;
            asm volatile("red.global.add.v4.f32 [%0], {%1, %2, %3, %4};"
                         :: "l"(yp + 64 + sub * 4), "f"(u0), "f"(u1), "f"(u2), "f"(u3) : "memory");
        }
    }
}

// ---------------------------------------------------------------------------
// Final GEMM: out[64n x 128o] = elu( z @ a^T ), z = [x | y/rs | w/rs] (K=320).
// ---------------------------------------------------------------------------
__global__ void __launch_bounds__(256) final_kernel(
    const float* __restrict__ x, float* __restrict__ out, int N)
{
    __shared__ float2 z_sm[64 * 65];      // [n][k] duplicated pairs
    __shared__ float  a_sm[64 * 132];     // [k][o]
    __shared__ float  inv_sm[64];

    const int tid = threadIdx.x;
    const int warp = tid >> 5, lane = tid & 31;
    const int n0 = blockIdx.x * 64;

    const int ob = (warp & 1) * 64;
    const int nb = (warp >> 1) * 16;
    const int nloc = nb + (lane >> 3) * 4;
    const int o0 = ob + (lane & 7) * 8;

    if (tid < 64) {
        float rs = (n0 + tid < N) ? g_rowsum[n0 + tid] : 0.f;
        inv_sm[tid] = rs > 0.f ? 1.f / rs : 0.f;
    }

    unsigned long long acc[4][4];
    #pragma unroll
    for (int j = 0; j < 4; j++)
        #pragma unroll
        for (int p = 0; p < 4; p++) acc[j][p] = 0ull;

    #pragma unroll
    for (int kc = 0; kc < 5; kc++) {
        __syncthreads();
        #pragma unroll
        for (int it = 0; it < 8; it++) {
            int i = tid + it * 256;
            int k = i >> 5, qq = i & 31;
            float4 av = *(const float4*)(g_aT + (size_t)(kc * 64 + k) * 128 + qq * 4);
            *(float4*)&a_sm[k * 132 + qq * 4] = av;
        }
        #pragma unroll
        for (int it = 0; it < 16; it++) {
            int i = tid + it * 256;
            int n = i >> 6, k = i & 63;
            float val = 0.f;
            if (n0 + n < N) {
                if (kc < 2)       val = x[(size_t)(n0 + n) * 128 + kc * 64 + k];
                else if (kc < 4)  val = g_y[(size_t)(n0 + n) * 128 + (kc - 2) * 64 + k] * inv_sm[n];
                else              val = g_w[(size_t)(n0 + n) * 64 + k] * inv_sm[n];
            }
            z_sm[n * 65 + k] = make_float2(val, val);
        }
        __syncthreads();

        #pragma unroll 8
        for (int k = 0; k < 64; k++) {
            ulonglong2 A01 = *(const ulonglong2*)&a_sm[k * 132 + o0];
            ulonglong2 A23 = *(const ulonglong2*)&a_sm[k * 132 + o0 + 4];
            #pragma unroll
            for (int j = 0; j < 4; j++) {
                unsigned long long zd = *(const unsigned long long*)&z_sm[(nloc + j) * 65 + k];
                fma2(acc[j][0], zd, A01.x);
                fma2(acc[j][1], zd, A01.y);
                fma2(acc[j][2], zd, A23.x);
                fma2(acc[j][3], zd, A23.y);
            }
        }
    }

    #pragma unroll
    for (int j = 0; j < 4; j++) {
        int n = n0 + nloc + j;
        if (n < N) {
            bool ok = inv_sm[nloc + j] > 0.f;
            float o[8];
            #pragma unroll
            for (int p = 0; p < 4; p++) {
                float2 f = unpack2(acc[j][p]);
                o[2 * p] = f.x; o[2 * p + 1] = f.y;
            }
            #pragma unroll
            for (int q = 0; q < 8; q++)
                o[q] = ok ? (o[q] > 0.f ? o[q] : expm1f(o[q])) : 0.f;
            float* dp = out + (size_t)n * 128 + o0;
            *(float4*)dp = make_float4(o[0], o[1], o[2], o[3]);
            *(float4*)(dp + 4) = make_float4(o[4], o[5], o[6], o[7]);
        }
    }
}

// ---------------------------------------------------------------------------
extern "C" void kernel_launch(void* const* d_in, const int* in_sizes, int n_in,
                              void* d_out, int out_size) {
    const float* x     = (const float*)d_in[0];
    const int*   edge1 = (const int*)  d_in[1];
    const float* emb1  = (const float*)d_in[2];
    const int*   edge2 = (const int*)  d_in[3];
    const float* emb2  = (const float*)d_in[4];
    const float* a     = (const float*)d_in[5];
    const float* a2    = (const float*)d_in[6];
    float* out = (float*)d_out;

    int N  = in_sizes[0] / 128;
    int E1 = in_sizes[1] / 2;
    int E2 = in_sizes[3] / 2;

    zero_kernel<<<1024, 256>>>(N);
    vec_kernel<<<1, 320>>>(a, a2);
    transpose_a_kernel<<<160, 256>>>(a);
    sdot_kernel<<<(N + 3) / 4, 128>>>(x, N);
    edge_kernel<<<592, 256>>>(edge1, emb1, edge2, emb2, x, E1, E2);
    final_kernel<<<(N + 63) / 64, 256>>>(x, out, N);
}